// round 4
// baseline (speedup 1.0000x reference)
#include <cuda_runtime.h>

#define DIMC 512
#define DIMK 128
#define HW   49
#define NSUP 25
#define NSAMP 26
#define NCOL (NSAMP * HW)          // 1274
#define PSTRIDE (NCOL * 256)       // one split-K partial plane

// Scratch (allocation-free)
__device__ float g_part[4 * PSTRIDE];   // [ks][(s*49+p)*256 + m]
__device__ float g_eu2[NSUP * 7];       // per (ng, ptile) euclid partials
__device__ int   g_cnt[NSUP];           // arrival counters (zero-init, self-resetting)

// ---- packed fp32x2 helpers (sm_10x) --------------------------------------
__device__ __forceinline__ unsigned long long pack2(float a, float b) {
    unsigned long long r;
    asm("mov.b64 %0, {%1, %2};" : "=l"(r) : "f"(a), "f"(b));
    return r;
}
__device__ __forceinline__ void fma2(unsigned long long& d,
                                     unsigned long long a, unsigned long long b) {
    asm("fma.rn.f32x2 %0, %1, %2, %0;" : "+l"(d) : "l"(a), "l"(b));
}
__device__ __forceinline__ float2 unpack2(unsigned long long v) {
    float2 f;
    asm("mov.b64 {%0, %1}, %2;" : "=f"(f.x), "=f"(f.y) : "l"(v));
    return f;
}

// ---------------------------------------------------------------------------
// Kernel A: split-K projection GEMM, low-LDS-traffic mapping.
//   Block = (sample, mt in 0..3 -> 64 rows of [Wqk;Wv], ks in 0..3 -> K-chunk 128).
//   128 threads: warp&1 selects 32-row slab (lane = row, conflict-free LDS.32),
//   warp>>1 selects 28-position slab (x loads are warp-broadcast LDS.128).
//   Each lane: 1 row x 28 positions in 14 packed f32x2 accumulators.
// ---------------------------------------------------------------------------
#define TPB_A 128
#define WPITCH 65   // == 1 mod 32: conflict-free transpose staging AND reads
#define XPITCH 56

__global__ void __launch_bounds__(TPB_A, 3)
kernelA(const float* __restrict__ query, const float* __restrict__ supports,
        const float* __restrict__ Wqk, const float* __restrict__ Wv)
{
    extern __shared__ float sm[];
    float* Ws = sm;                    // [128 c][WPITCH]  (c-major, row inner)
    float* Xs = sm + 128 * WPITCH;     // [128 c][XPITCH]  (c-major, pos inner)

    const int s  = blockIdx.x;         // 0..25 (25 == query)
    const int mt = blockIdx.y;         // 0..3
    const int ks = blockIdx.z;         // 0..3
    const int c0 = ks * 128;
    const float* W    = (mt < 2) ? Wqk : Wv;
    const int wrow0   = (mt & 1) * 64;
    const float* X    = (s == NSUP) ? query : supports + (size_t)s * DIMC * HW;

    const int tid = threadIdx.x;

    // Stage W: 64 rows x 128 c. Thread tid owns column c = tid.
    // gmem read coalesced along c; smem write stride WPITCH==65 -> conflict-free.
    {
        const float* wg = W + (size_t)wrow0 * DIMC + c0 + tid;
        float* wsd = Ws + tid * WPITCH;
#pragma unroll 8
        for (int o = 0; o < 64; o++)
            wsd[o] = wg[o * DIMC];
    }
    // Stage X: 128 c x 56 pos (zero-pad 49..55)
    for (int e = tid; e < 128 * XPITCH; e += TPB_A) {
        int c = e / XPITCH, p = e - c * XPITCH;
        Xs[e] = (p < HW) ? X[(c0 + c) * HW + p] : 0.f;
    }
    __syncthreads();

    const int warp = tid >> 5, lane = tid & 31;
    const int o  = (warp & 1) * 32 + lane;   // row in 0..63
    const int ph = warp >> 1;                // pos slab: 0 -> 0..27, 1 -> 28..55

    const float* wb = Ws + o;
    const float* xb = Xs + ph * 28;

    unsigned long long acc[14];
#pragma unroll
    for (int i = 0; i < 14; i++) acc[i] = 0ull;

#pragma unroll 4
    for (int c = 0; c < 128; c++) {
        float w = wb[c * WPITCH];                    // conflict-free LDS.32
        unsigned long long w2 = pack2(w, w);
        const float* xr = xb + c * XPITCH;
#pragma unroll
        for (int i = 0; i < 7; i++) {
            ulonglong2 xv = *(const ulonglong2*)(xr + i * 4);  // warp-broadcast
            fma2(acc[2 * i],     w2, xv.x);
            fma2(acc[2 * i + 1], w2, xv.y);
        }
    }

    // Epilogue: m in [0,256): mt*64+o (qk rows then v rows). Coalesced per-p STG.
    const int m = mt * 64 + o;
    float* base = g_part + (size_t)ks * PSTRIDE + (size_t)(s * HW) * 256 + m;
#pragma unroll
    for (int i = 0; i < 14; i++) {
        float2 v = unpack2(acc[i]);
        int p0 = ph * 28 + 2 * i;
        if (p0 < HW)     base[(size_t)p0 * 256]       = v.x;
        if (p0 + 1 < HW) base[(size_t)(p0 + 1) * 256] = v.y;
    }
}

// ---------------------------------------------------------------------------
// Kernel B: fused partial-reduce + attention + euclid + final output.
//   Grid (n, 7): block handles group ng and 7 query positions pt*7+pl.
//   Stages summed sk tile -> sims -> softmax stats -> restage sv -> AV ->
//   euclid partial -> last block per ng reduces deterministically into out.
// ---------------------------------------------------------------------------
#define TPB_B 256
#define KTILE 245
#define SKP   132          // sk/sv smem pitch (4-way worst case on dot reads)
#define PJMAX 1232         // sims row pitch (worst case nkeys = 1225)

__global__ void __launch_bounds__(TPB_B, 1)
kernelB(float* __restrict__ out, int n, int k)
{
    extern __shared__ float bsm[];
    float* skv   = bsm;                       // [KTILE][SKP]
    float* sims  = skv + KTILE * SKP;         // [7][PJMAX]
    float* qq_s  = sims + 7 * PJMAX;          // [7][128]
    float* qv_s  = qq_s + 7 * 128;            // [7][128]
    float* outsh = qv_s + 7 * 128;            // [7][128]
    float* invsh = outsh + 7 * 128;           // [7]  softmax 1/sum
    float* redsh = invsh + 8;                 // [8]  block reduce

    const int ng = blockIdx.x;
    const int pt = blockIdx.y;                // 0..6
    const int nkeys = k * HW;
    const int tid = threadIdx.x;
    const float SCALE = 0.08838834764831845f; // 128^-0.5

    // Stage qq/qv for 7 positions (sum 4 split-K partials; query sample s=25)
    for (int e = tid; e < 7 * 256; e += TPB_B) {
        int pl = e >> 8, m = e & 255;
        size_t idx = (size_t)(NSUP * HW + pt * 7 + pl) * 256 + m;
        float v = g_part[idx] + g_part[PSTRIDE + idx]
                + g_part[2 * PSTRIDE + idx] + g_part[3 * PSTRIDE + idx];
        if (m < 128) qq_s[pl * 128 + m] = v;
        else         qv_s[pl * 128 + (m - 128)] = v;
    }

    // ---- Pass 1: sims over key tiles ----
    for (int t0 = 0; t0 < nkeys; t0 += KTILE) {
        int tn = min(KTILE, nkeys - t0);
        __syncthreads();
        // stage summed sk tile (x0.5 analytic sigmoid factor)
        for (int e = tid; e < tn * 128; e += TPB_B) {
            int key = e >> 7, oo = e & 127;
            int gk = t0 + key;
            int kk = gk / HW, ij = gk - kk * HW;
            size_t idx = (size_t)((ng * k + kk) * HW + ij) * 256 + oo;
            float v = g_part[idx] + g_part[PSTRIDE + idx]
                    + g_part[2 * PSTRIDE + idx] + g_part[3 * PSTRIDE + idx];
            skv[key * SKP + oo] = 0.5f * v;
        }
        __syncthreads();
        // thread-per-key dot against 7 query positions (qq reads broadcast)
        for (int j = tid; j < tn; j += TPB_B) {
            const float4* sk4 = (const float4*)(skv + j * SKP);
            float a[7] = {0, 0, 0, 0, 0, 0, 0};
#pragma unroll 4
            for (int o4 = 0; o4 < 32; o4++) {
                float4 x = sk4[o4];
#pragma unroll
                for (int pl = 0; pl < 7; pl++) {
                    float4 q = *(const float4*)(qq_s + pl * 128 + o4 * 4);
                    a[pl] += x.x * q.x + x.y * q.y + x.z * q.z + x.w * q.w;
                }
            }
#pragma unroll
            for (int pl = 0; pl < 7; pl++)
                sims[pl * PJMAX + t0 + j] = a[pl] * SCALE;
        }
    }
    __syncthreads();

    // ---- Softmax stats: warp pl handles row pl; store exp in place, inv sum ----
    if (tid < 7 * 32) {
        int pl = tid >> 5, l = tid & 31;
        float* row = sims + pl * PJMAX;
        float m = -1e30f;
        for (int j = l; j < nkeys; j += 32) m = fmaxf(m, row[j]);
#pragma unroll
        for (int off = 16; off; off >>= 1) m = fmaxf(m, __shfl_xor_sync(~0u, m, off));
        float sum = 0.f;
        for (int j = l; j < nkeys; j += 32) {
            float e = __expf(row[j] - m);
            row[j] = e;
            sum += e;
        }
#pragma unroll
        for (int off = 16; off; off >>= 1) sum += __shfl_xor_sync(~0u, sum, off);
        if (l == 0) invsh[pl] = 1.f / sum;
    }

    // ---- Pass 2: AV over key tiles (sv restaged into skv buffer) ----
    const int o  = tid & 127;
    const int hf = tid >> 7;
    float acc7[7] = {0, 0, 0, 0, 0, 0, 0};

    for (int t0 = 0; t0 < nkeys; t0 += KTILE) {
        int tn = min(KTILE, nkeys - t0);
        __syncthreads();
        for (int e = tid; e < tn * 128; e += TPB_B) {
            int key = e >> 7, oo = e & 127;
            int gk = t0 + key;
            int kk = gk / HW, ij = gk - kk * HW;
            size_t idx = (size_t)((ng * k + kk) * HW + ij) * 256 + 128 + oo;
            float v = g_part[idx] + g_part[PSTRIDE + idx]
                    + g_part[2 * PSTRIDE + idx] + g_part[3 * PSTRIDE + idx];
            skv[key * SKP + oo] = 0.5f * v;
        }
        __syncthreads();
        for (int j = hf; j < tn; j += 2) {
            float sv = skv[j * SKP + o];          // conflict-free (lanes = o)
            const float* att = sims + t0 + j;     // broadcast reads
#pragma unroll
            for (int pl = 0; pl < 7; pl++)
                acc7[pl] += att[pl * PJMAX] * sv;
        }
    }

    __syncthreads();
    if (hf == 0) {
#pragma unroll
        for (int pl = 0; pl < 7; pl++) outsh[pl * 128 + o] = acc7[pl];
    }
    __syncthreads();
    if (hf == 1) {
#pragma unroll
        for (int pl = 0; pl < 7; pl++) outsh[pl * 128 + o] += acc7[pl];
    }
    __syncthreads();

    // ---- Euclid partial over (7 positions x 128 channels) ----
    float e2 = 0.f;
    if (tid < 128) {
#pragma unroll
        for (int pl = 0; pl < 7; pl++) {
            float d = qv_s[pl * 128 + tid] - outsh[pl * 128 + tid] * invsh[pl];
            e2 += d * d;
        }
    }
#pragma unroll
    for (int off = 16; off; off >>= 1) e2 += __shfl_xor_sync(~0u, e2, off);
    if ((tid & 31) == 0) redsh[tid >> 5] = e2;
    __syncthreads();

    if (tid == 0) {
        float t = 0.f;
#pragma unroll
        for (int w = 0; w < 8; w++) t += redsh[w];
        g_eu2[ng * 7 + pt] = t;
        __threadfence();
        int old = atomicAdd(&g_cnt[ng], 1);
        if (old == 6) {                       // last of the 7 ptile blocks
            __threadfence();
            volatile float* ve = g_eu2 + ng * 7;
            float s = 0.f;
            for (int i = 0; i < 7; i++) s += ve[i];   // fixed order: deterministic
            out[ng] = -s / 49.0f;
            g_cnt[ng] = 0;                    // reset for next graph replay
        }
    }
}

// ---------------------------------------------------------------------------
extern "C" void kernel_launch(void* const* d_in, const int* in_sizes, int n_in,
                              void* d_out, int out_size)
{
    const float* query    = (const float*)d_in[0];   // (1,512,7,7)
    const float* supports = (const float*)d_in[1];   // (25,512,7,7)
    const float* Wqk      = (const float*)d_in[2];   // (128,512)
    const float* Wv       = (const float*)d_in[3];   // (128,512)
    float* out = (float*)d_out;

    int n = out_size;
    if (n <= 0 || n > NSUP) n = 5;
    int k = NSUP / n;

    const int smemA = (128 * WPITCH + 128 * XPITCH) * sizeof(float);   // 61,952 B
    const int smemB = (KTILE * SKP + 7 * PJMAX + 3 * 7 * 128 + 16) * sizeof(float); // ~174.7 KB
    cudaFuncSetAttribute(kernelA, cudaFuncAttributeMaxDynamicSharedMemorySize, smemA);
    cudaFuncSetAttribute(kernelB, cudaFuncAttributeMaxDynamicSharedMemorySize, smemB);

    kernelA<<<dim3(NSAMP, 4, 4), TPB_A, smemA>>>(query, supports, Wqk, Wv);
    kernelB<<<dim3(n, 7), TPB_B, smemB>>>(out, n, k);
}

// round 5
// speedup vs baseline: 1.3898x; 1.3898x over previous
#include <cuda_runtime.h>

#define DIMC 512
#define DIMK 128
#define HW   49
#define NSUP 25
#define NSAMP 26
#define NCOL (NSAMP * HW)          // 1274
#define PSTRIDE (NCOL * 256)       // one split-K partial plane

// Scratch (allocation-free)
__device__ float g_part[4 * PSTRIDE];     // [ks][(s*49+p)*256 + m]
__device__ float g_qq[HW * DIMK];         // [p][o]
__device__ float g_qv[HW * DIMK];         // [p][o]
__device__ float g_sk[NSUP * HW * DIMK];  // [(s*49+p)][o]  (0.5x applied)
__device__ float g_sv[NSUP * HW * DIMK];
__device__ float g_eu[NSUP * HW];         // per-(ng,p) euclid partials
__device__ int   g_cnt[NSUP];             // arrival counters (self-resetting)

// ---- packed fp32x2 helpers (sm_10x) --------------------------------------
__device__ __forceinline__ unsigned long long pack2(float a, float b) {
    unsigned long long r;
    asm("mov.b64 %0, {%1, %2};" : "=l"(r) : "f"(a), "f"(b));
    return r;
}
__device__ __forceinline__ void fma2(unsigned long long& d,
                                     unsigned long long a, unsigned long long b) {
    asm("fma.rn.f32x2 %0, %1, %2, %0;" : "+l"(d) : "l"(a), "l"(b));
}
__device__ __forceinline__ float2 unpack2(unsigned long long v) {
    float2 f;
    asm("mov.b64 {%0, %1}, %2;" : "=f"(f.x), "=f"(f.y) : "l"(v));
    return f;
}

// ---------------------------------------------------------------------------
// Kernel A: split-K projection GEMM (unchanged from R4 — ~6us, near FFMA2 floor)
// ---------------------------------------------------------------------------
#define TPB_A 128
#define WPITCH 65
#define XPITCH 56

__global__ void __launch_bounds__(TPB_A, 3)
kernelA(const float* __restrict__ query, const float* __restrict__ supports,
        const float* __restrict__ Wqk, const float* __restrict__ Wv)
{
    extern __shared__ float sm[];
    float* Ws = sm;                    // [128 c][WPITCH]
    float* Xs = sm + 128 * WPITCH;     // [128 c][XPITCH]

    const int s  = blockIdx.x;
    const int mt = blockIdx.y;
    const int ks = blockIdx.z;
    const int c0 = ks * 128;
    const float* W    = (mt < 2) ? Wqk : Wv;
    const int wrow0   = (mt & 1) * 64;
    const float* X    = (s == NSUP) ? query : supports + (size_t)s * DIMC * HW;

    const int tid = threadIdx.x;

    {
        const float* wg = W + (size_t)wrow0 * DIMC + c0 + tid;
        float* wsd = Ws + tid * WPITCH;
#pragma unroll 8
        for (int o = 0; o < 64; o++)
            wsd[o] = wg[o * DIMC];
    }
    for (int e = tid; e < 128 * XPITCH; e += TPB_A) {
        int c = e / XPITCH, p = e - c * XPITCH;
        Xs[e] = (p < HW) ? X[(c0 + c) * HW + p] : 0.f;
    }
    __syncthreads();

    const int warp = tid >> 5, lane = tid & 31;
    const int o  = (warp & 1) * 32 + lane;
    const int ph = warp >> 1;

    const float* wb = Ws + o;
    const float* xb = Xs + ph * 28;

    unsigned long long acc[14];
#pragma unroll
    for (int i = 0; i < 14; i++) acc[i] = 0ull;

#pragma unroll 4
    for (int c = 0; c < 128; c++) {
        float w = wb[c * WPITCH];
        unsigned long long w2 = pack2(w, w);
        const float* xr = xb + c * XPITCH;
#pragma unroll
        for (int i = 0; i < 7; i++) {
            ulonglong2 xv = *(const ulonglong2*)(xr + i * 4);
            fma2(acc[2 * i],     w2, xv.x);
            fma2(acc[2 * i + 1], w2, xv.y);
        }
    }

    const int m = mt * 64 + o;
    float* base = g_part + (size_t)ks * PSTRIDE + (size_t)(s * HW) * 256 + m;
#pragma unroll
    for (int i = 0; i < 14; i++) {
        float2 v = unpack2(acc[i]);
        int p0 = ph * 28 + 2 * i;
        if (p0 < HW)     base[(size_t)p0 * 256]       = v.x;
        if (p0 + 1 < HW) base[(size_t)(p0 + 1) * 256] = v.y;
    }
}

// ---------------------------------------------------------------------------
// Kernel R: collapse 4 split-K planes into compact layouts (once).
//   grid NCOL x 256. Coalesced read/write, 13 MB total -> ~1.5us.
// ---------------------------------------------------------------------------
__global__ void __launch_bounds__(256)
kernelR()
{
    const int n = blockIdx.x;          // (s*49+p)
    const int m = threadIdx.x;         // 0..255
    const size_t idx = (size_t)n * 256 + m;
    float v = g_part[idx] + g_part[PSTRIDE + idx]
            + g_part[2 * PSTRIDE + idx] + g_part[3 * PSTRIDE + idx];

    const int s = n / HW;
    const int p = n - s * HW;
    const int o = m & 127;
    if (s == NSUP) {
        if (m < 128) g_qq[p * DIMK + o] = v;
        else         g_qv[p * DIMK + o] = v;
    } else {
        v *= 0.5f;                     // analytic sigmoid factor
        if (m < 128) g_sk[(size_t)n * DIMK + o] = v;
        else         g_sv[(size_t)n * DIMK + o] = v;
    }
}

// ---------------------------------------------------------------------------
// Kernel B: attention for a PAIR of query positions per block.
//   grid (n, 25): block (ng, pt) handles p0=2*pt, p1=p0+1 (p1 may be absent).
//   sk/sv stream from L2 (coalesced); sims+q in smem. Final output fused via
//   deterministic last-arrival reduction.
// ---------------------------------------------------------------------------
#define TPB_B 256
#define SIMP  256          // sims row pitch (nkeys <= 245 for n=5; guard below)

__global__ void __launch_bounds__(TPB_B, 4)
kernelB(float* __restrict__ out, int n, int k)
{
    const int ng = blockIdx.x;
    const int pt = blockIdx.y;           // 0..24
    const int p0 = 2 * pt;
    const int np = (p0 + 1 < HW) ? 2 : 1;
    const int nkeys = k * HW;            // 245 for n=5

    __shared__ float q0[DIMK], q1[DIMK];
    __shared__ float sims[2 * SIMP];
    __shared__ float osh[2 * DIMK];
    __shared__ float invsh[2];
    __shared__ float redsh[8];

    const int tid = threadIdx.x;
    const float SCALE = 0.08838834764831845f;  // 128^-0.5

    if (tid < DIMK) {
        q0[tid] = g_qq[p0 * DIMK + tid];
        q1[tid] = (np == 2) ? g_qq[(p0 + 1) * DIMK + tid] : 0.f;
    }
    __syncthreads();

    // ---- sims: thread-per-key, 32 independent LDG.128 per key ----
    const float* skbase = g_sk + (size_t)(ng * k * HW) * DIMK;
    for (int j = tid; j < nkeys; j += TPB_B) {
        const float4* sk4 = (const float4*)(skbase + (size_t)j * DIMK);
        float a0 = 0.f, b0 = 0.f, a1 = 0.f, b1 = 0.f;
#pragma unroll
        for (int o4 = 0; o4 < 32; o4 += 2) {
            float4 x = sk4[o4], y = sk4[o4 + 1];
            float4 qa = *(const float4*)(q0 + o4 * 4);
            float4 qb = *(const float4*)(q0 + o4 * 4 + 4);
            a0 += x.x * qa.x + x.y * qa.y + x.z * qa.z + x.w * qa.w;
            b0 += y.x * qb.x + y.y * qb.y + y.z * qb.z + y.w * qb.w;
            float4 ra = *(const float4*)(q1 + o4 * 4);
            float4 rb = *(const float4*)(q1 + o4 * 4 + 4);
            a1 += x.x * ra.x + x.y * ra.y + x.z * ra.z + x.w * ra.w;
            b1 += y.x * rb.x + y.y * rb.y + y.z * rb.z + y.w * rb.w;
        }
        sims[j]        = (a0 + b0) * SCALE;
        sims[SIMP + j] = (a1 + b1) * SCALE;
    }
    __syncthreads();

    // ---- softmax stats: warp 0 -> p0, warp 1 -> p1 ----
    if (tid < 64) {
        int pl = tid >> 5, l = tid & 31;
        if (pl < np) {
            float* row = sims + pl * SIMP;
            float m = -1e30f;
            for (int j = l; j < nkeys; j += 32) m = fmaxf(m, row[j]);
#pragma unroll
            for (int off = 16; off; off >>= 1) m = fmaxf(m, __shfl_xor_sync(~0u, m, off));
            float sum = 0.f;
            for (int j = l; j < nkeys; j += 32) {
                float e = __expf(row[j] - m);
                row[j] = e;
                sum += e;
            }
#pragma unroll
            for (int off = 16; off; off >>= 1) sum += __shfl_xor_sync(~0u, sum, off);
            if (l == 0) invsh[pl] = 1.f / sum;
        }
    }
    __syncthreads();

    // ---- AV: thread = (o, half); sv coalesced from L2, attn broadcast ----
    const int o  = tid & 127;
    const int hf = tid >> 7;
    const float* svbase = g_sv + (size_t)(ng * k * HW) * DIMK + o;
    float c0a = 0.f, c1a = 0.f;
    int j = hf;
    for (; j + 6 < nkeys; j += 8) {     // unroll x4 (stride 2) for MLP
        float v0 = svbase[(size_t)(j)     * DIMK];
        float v1 = svbase[(size_t)(j + 2) * DIMK];
        float v2 = svbase[(size_t)(j + 4) * DIMK];
        float v3 = svbase[(size_t)(j + 6) * DIMK];
        c0a += sims[j] * v0 + sims[j + 2] * v1 + sims[j + 4] * v2 + sims[j + 6] * v3;
        c1a += sims[SIMP + j] * v0 + sims[SIMP + j + 2] * v1
             + sims[SIMP + j + 4] * v2 + sims[SIMP + j + 6] * v3;
    }
    for (; j < nkeys; j += 2) {
        float v = svbase[(size_t)j * DIMK];
        c0a += sims[j] * v;
        c1a += sims[SIMP + j] * v;
    }

    if (hf == 0) { osh[o] = c0a; osh[DIMK + o] = c1a; }
    __syncthreads();
    if (hf == 1) { osh[o] += c0a; osh[DIMK + o] += c1a; }
    __syncthreads();

    // ---- euclid partials for both positions ----
    float e2 = 0.f;
    if (tid < DIMK) {
        float d0 = g_qv[p0 * DIMK + tid] - osh[tid] * invsh[0];
        e2 = d0 * d0;
        if (np == 2) {
            float d1 = g_qv[(p0 + 1) * DIMK + tid] - osh[DIMK + tid] * invsh[1];
            e2 += d1 * d1;
        }
    }
#pragma unroll
    for (int off = 16; off; off >>= 1) e2 += __shfl_xor_sync(~0u, e2, off);
    if ((tid & 31) == 0) redsh[tid >> 5] = e2;
    __syncthreads();

    if (tid == 0) {
        float t = 0.f;
#pragma unroll
        for (int w = 0; w < 8; w++) t += redsh[w];
        g_eu[ng * 25 + pt] = t;
        __threadfence();
        int old = atomicAdd(&g_cnt[ng], 1);
        if (old == 24) {                 // last of 25 blocks for this group
            __threadfence();
            volatile float* ve = g_eu + ng * 25;
            float s = 0.f;
            for (int i = 0; i < 25; i++) s += ve[i];   // fixed order
            out[ng] = -s / 49.0f;
            g_cnt[ng] = 0;               // reset for next graph replay
        }
    }
}

// ---------------------------------------------------------------------------
extern "C" void kernel_launch(void* const* d_in, const int* in_sizes, int n_in,
                              void* d_out, int out_size)
{
    const float* query    = (const float*)d_in[0];
    const float* supports = (const float*)d_in[1];
    const float* Wqk      = (const float*)d_in[2];
    const float* Wv       = (const float*)d_in[3];
    float* out = (float*)d_out;

    int n = out_size;
    if (n <= 0 || n > NSUP) n = 5;
    int k = NSUP / n;

    const int smemA = (128 * WPITCH + 128 * XPITCH) * sizeof(float);  // 61,952 B
    cudaFuncSetAttribute(kernelA, cudaFuncAttributeMaxDynamicSharedMemorySize, smemA);

    kernelA<<<dim3(NSAMP, 4, 4), TPB_A, smemA>>>(query, supports, Wqk, Wv);
    kernelR<<<NCOL, 256>>>();
    kernelB<<<dim3(n, 25), TPB_B>>>(out, n, k);
}